// round 1
// baseline (speedup 1.0000x reference)
#include <cuda_runtime.h>
#include <cstdint>

// Problem constants (fixed by the dataset)
#define N_NODES 100000
#define N_EDGES 800000
#define IN_SIZE 128
#define OUT_SIZE 64

// ---------------------------------------------------------------------------
// Scratch (no cudaMalloc allowed) — ~57.6 MB static device memory
// ---------------------------------------------------------------------------
__device__ int   g_is64;
__device__ int   g_src32[N_EDGES];
__device__ int   g_tgt32[N_EDGES];
__device__ int   g_rowptr[N_NODES + 1];
__device__ __align__(16) float g_buf0[(size_t)N_NODES * OUT_SIZE];
__device__ __align__(16) float g_buf1[(size_t)N_NODES * OUT_SIZE];

// ---------------------------------------------------------------------------
// 1) Detect whether index buffers are int64 or int32.
//    src_idx is uniform random in [0, N_NODES); if the buffer is really int32,
//    reading it as int64 combines two 32-bit values -> value >= 2^32 almost
//    surely within 32 samples (P[miss] ~ (1e-5)^32).
// ---------------------------------------------------------------------------
__global__ void detect_kernel(const void* src_any) {
    if (threadIdx.x == 0) {
        const long long* p = (const long long*)src_any;
        int is64 = 1;
        for (int i = 0; i < 32; ++i) {
            long long v = p[i];
            if (v < 0 || v >= (long long)N_NODES) { is64 = 0; break; }
        }
        g_is64 = is64;
    }
}

// ---------------------------------------------------------------------------
// 2) Normalize indices to int32 scratch.
// ---------------------------------------------------------------------------
__global__ void convert_kernel(const void* src_any, const void* tgt_any) {
    int i = blockIdx.x * blockDim.x + threadIdx.x;
    if (i >= N_EDGES) return;
    if (g_is64) {
        g_src32[i] = (int)((const long long*)src_any)[i];
        g_tgt32[i] = (int)((const long long*)tgt_any)[i];
    } else {
        g_src32[i] = ((const int*)src_any)[i];
        g_tgt32[i] = ((const int*)tgt_any)[i];
    }
}

// ---------------------------------------------------------------------------
// 3) row_ptr via per-node lower_bound in the sorted tgt array.
//    t in [0, N_NODES]; lower_bound(N_NODES) == N_EDGES naturally.
// ---------------------------------------------------------------------------
__global__ void rowptr_kernel() {
    int t = blockIdx.x * blockDim.x + threadIdx.x;
    if (t > N_NODES) return;
    int lo = 0, hi = N_EDGES;
    while (lo < hi) {
        int mid = (lo + hi) >> 1;
        if (g_tgt32[mid] < t) lo = mid + 1; else hi = mid;
    }
    g_rowptr[t] = lo;
}

// ---------------------------------------------------------------------------
// 4) GEMM: Y = X @ W + b   (100000x128 @ 128x64, fp32)
//    W (32 KB) staged in smem. Each warp processes 4 rows at a time; each lane
//    owns 2 adjacent output columns (2*lane, 2*lane+1) so loads/stores are
//    natural-layout float2. X rows read via broadcast __ldg float4.
// ---------------------------------------------------------------------------
__global__ __launch_bounds__(256) void gemm_kernel(const float* __restrict__ X,
                                                   const float* __restrict__ W,
                                                   const float* __restrict__ b) {
    __shared__ float Ws[IN_SIZE * OUT_SIZE];  // 32 KB, natural layout [k][j]

    // cooperative load of W into smem
    for (int i = threadIdx.x; i < IN_SIZE * OUT_SIZE; i += blockDim.x)
        Ws[i] = W[i];
    __syncthreads();

    const int lane   = threadIdx.x & 31;
    const int warpId = threadIdx.x >> 5;
    const int gw     = blockIdx.x * 8 + warpId;      // global warp id
    const int nWarps = gridDim.x * 8;

    const float2 bb = ((const float2*)b)[lane];      // cols (2*lane, 2*lane+1)
    float2* __restrict__ Y2 = (float2*)g_buf0;

    const int nGroups = N_NODES / 4;                 // 25000, exact
    for (int g = gw; g < nGroups; g += nWarps) {
        const int r0 = g * 4;
        const float4* xr0 = (const float4*)(X + (size_t)(r0 + 0) * IN_SIZE);
        const float4* xr1 = (const float4*)(X + (size_t)(r0 + 1) * IN_SIZE);
        const float4* xr2 = (const float4*)(X + (size_t)(r0 + 2) * IN_SIZE);
        const float4* xr3 = (const float4*)(X + (size_t)(r0 + 3) * IN_SIZE);

        float2 a0 = {0.f, 0.f}, a1 = {0.f, 0.f}, a2 = {0.f, 0.f}, a3 = {0.f, 0.f};

        #pragma unroll 2
        for (int k4 = 0; k4 < IN_SIZE / 4; ++k4) {   // 32 iterations
            float4 x0 = __ldg(xr0 + k4);
            float4 x1 = __ldg(xr1 + k4);
            float4 x2 = __ldg(xr2 + k4);
            float4 x3 = __ldg(xr3 + k4);
            #pragma unroll
            for (int kk = 0; kk < 4; ++kk) {
                const float2 w = *(const float2*)&Ws[(k4 * 4 + kk) * OUT_SIZE + 2 * lane];
                const float e0 = ((const float*)&x0)[kk];
                const float e1 = ((const float*)&x1)[kk];
                const float e2 = ((const float*)&x2)[kk];
                const float e3 = ((const float*)&x3)[kk];
                a0.x += e0 * w.x; a0.y += e0 * w.y;
                a1.x += e1 * w.x; a1.y += e1 * w.y;
                a2.x += e2 * w.x; a2.y += e2 * w.y;
                a3.x += e3 * w.x; a3.y += e3 * w.y;
            }
        }
        Y2[(r0 + 0) * 32 + lane] = make_float2(a0.x + bb.x, a0.y + bb.y);
        Y2[(r0 + 1) * 32 + lane] = make_float2(a1.x + bb.x, a1.y + bb.y);
        Y2[(r0 + 2) * 32 + lane] = make_float2(a2.x + bb.x, a2.y + bb.y);
        Y2[(r0 + 3) * 32 + lane] = make_float2(a3.x + bb.x, a3.y + bb.y);
    }
}

// ---------------------------------------------------------------------------
// 5) Propagation: one warp per node.
//    new[t] = (deg>0) ? (in[t] + sum_{e in seg(t)} in[src[e]]) / (deg+1) : 0
//    stage 0: g_buf0 -> g_buf1
//    stage 1: g_buf1 -> d_out, with ReLU
// ---------------------------------------------------------------------------
__global__ __launch_bounds__(256) void prop_kernel(float* __restrict__ dout, int stage) {
    const int gw   = (blockIdx.x * blockDim.x + threadIdx.x) >> 5;
    const int lane = threadIdx.x & 31;
    if (gw >= N_NODES) return;
    const int t = gw;

    const float2* __restrict__ in2  = (stage == 0) ? (const float2*)g_buf0 : (const float2*)g_buf1;
    float2*       __restrict__ out2 = (stage == 0) ? (float2*)g_buf1       : (float2*)dout;

    const int start = g_rowptr[t];
    const int end   = g_rowptr[t + 1];
    const int deg   = end - start;

    if (deg == 0) {
        out2[t * 32 + lane] = make_float2(0.f, 0.f);
        return;
    }

    float2 acc = make_float2(0.f, 0.f);
    int e = start;
    for (; e + 4 <= end; e += 4) {
        const int s0 = __ldg(&g_src32[e + 0]);
        const int s1 = __ldg(&g_src32[e + 1]);
        const int s2 = __ldg(&g_src32[e + 2]);
        const int s3 = __ldg(&g_src32[e + 3]);
        const float2 v0 = __ldg(&in2[s0 * 32 + lane]);
        const float2 v1 = __ldg(&in2[s1 * 32 + lane]);
        const float2 v2 = __ldg(&in2[s2 * 32 + lane]);
        const float2 v3 = __ldg(&in2[s3 * 32 + lane]);
        acc.x += (v0.x + v1.x) + (v2.x + v3.x);
        acc.y += (v0.y + v1.y) + (v2.y + v3.y);
    }
    for (; e < end; ++e) {
        const int s = __ldg(&g_src32[e]);
        const float2 v = __ldg(&in2[s * 32 + lane]);
        acc.x += v.x; acc.y += v.y;
    }

    const float2 own = __ldg(&in2[t * 32 + lane]);
    const float sc = 1.0f / (float)(deg + 1);
    float2 r = make_float2((acc.x + own.x) * sc, (acc.y + own.y) * sc);
    if (stage == 1) { r.x = fmaxf(r.x, 0.f); r.y = fmaxf(r.y, 0.f); }
    out2[t * 32 + lane] = r;
}

// ---------------------------------------------------------------------------
// Launch. Inputs (metadata order): data, W, b, src_idx, tgt_idx
// ---------------------------------------------------------------------------
extern "C" void kernel_launch(void* const* d_in, const int* in_sizes, int n_in,
                              void* d_out, int out_size) {
    const float* X = (const float*)d_in[0];
    const float* W = (const float*)d_in[1];
    const float* b = (const float*)d_in[2];
    const void*  src = d_in[3];
    const void*  tgt = d_in[4];
    float* out = (float*)d_out;

    detect_kernel<<<1, 32>>>(src);
    convert_kernel<<<(N_EDGES + 255) / 256, 256>>>(src, tgt);
    rowptr_kernel<<<(N_NODES + 1 + 255) / 256, 256>>>();
    gemm_kernel<<<592, 256>>>(X, W, b);
    const int propBlocks = (N_NODES * 32 + 255) / 256;  // 1 warp/node
    prop_kernel<<<propBlocks, 256>>>(out, 0);
    prop_kernel<<<propBlocks, 256>>>(out, 1);
}

// round 2
// speedup vs baseline: 1.2163x; 1.2163x over previous
#include <cuda_runtime.h>
#include <cstdint>

// Problem constants (fixed by the dataset)
#define N_NODES 100000
#define N_EDGES 800000
#define IN_SIZE 128
#define OUT_SIZE 64

// ---------------------------------------------------------------------------
// Scratch (no cudaMalloc allowed)
// ---------------------------------------------------------------------------
__device__ int   g_is64;
__device__ int   g_src32[N_EDGES];
__device__ int   g_tgt32[N_EDGES];
__device__ int   g_rowptr[N_NODES + 1];
__device__ __align__(16) float g_buf0[(size_t)N_NODES * OUT_SIZE];
__device__ __align__(16) float g_buf1[(size_t)N_NODES * OUT_SIZE];

// ---------------------------------------------------------------------------
// 1) Detect whether index buffers are int64 or int32.
// ---------------------------------------------------------------------------
__global__ void detect_kernel(const void* src_any) {
    if (threadIdx.x == 0) {
        const long long* p = (const long long*)src_any;
        int is64 = 1;
        for (int i = 0; i < 32; ++i) {
            long long v = p[i];
            if (v < 0 || v >= (long long)N_NODES) { is64 = 0; break; }
        }
        g_is64 = is64;
    }
}

// ---------------------------------------------------------------------------
// 2) Normalize indices to int32 scratch.
// ---------------------------------------------------------------------------
__global__ void convert_kernel(const void* src_any, const void* tgt_any) {
    int i = blockIdx.x * blockDim.x + threadIdx.x;
    if (i >= N_EDGES) return;
    if (g_is64) {
        g_src32[i] = (int)((const long long*)src_any)[i];
        g_tgt32[i] = (int)((const long long*)tgt_any)[i];
    } else {
        g_src32[i] = ((const int*)src_any)[i];
        g_tgt32[i] = ((const int*)tgt_any)[i];
    }
}

// ---------------------------------------------------------------------------
// 3) row_ptr via per-node lower_bound in the sorted tgt array.
// ---------------------------------------------------------------------------
__global__ void rowptr_kernel() {
    int t = blockIdx.x * blockDim.x + threadIdx.x;
    if (t > N_NODES) return;
    int lo = 0, hi = N_EDGES;
    while (lo < hi) {
        int mid = (lo + hi) >> 1;
        if (g_tgt32[mid] < t) lo = mid + 1; else hi = mid;
    }
    g_rowptr[t] = lo;
}

// ---------------------------------------------------------------------------
// 4) GEMM: Y = X @ W + b   (100000x128 @ 128x64, fp32)
//    Register-tiled: block computes 256 rows x 64 cols, thread tile 8x8.
//    X staged transposed in smem (XsT[k][row], pad->260) so the 8-row read per
//    k is 2x LDS.128 conflict-free (all lanes share k). W tile in smem.
//    Per thread per k: 4 LDS.128 -> 64 FMA. Gmem prefetch 1 k-tile ahead.
// ---------------------------------------------------------------------------
__global__ __launch_bounds__(256, 2) void gemm_kernel(const float* __restrict__ X,
                                                      const float* __restrict__ W,
                                                      const float* __restrict__ b) {
    __shared__ float XsT[16][260];   // [k][row], pad 256->260 (keeps 16B align)
    __shared__ float Ws[16][64];     // [k][col]

    const int tid = threadIdx.x;
    const int tr  = tid >> 3;        // 0..31  -> rows tr*8 .. tr*8+7
    const int tc  = tid & 7;         // 0..7   -> cols tc*8 .. tc*8+7
    const int rowBase = blockIdx.x * 256;

    // gmem-load mapping: thread covers 4 rows (lr + 64p), 16B k-chunk at lk
    const int lr = tid >> 2;         // 0..63
    const int lk = (tid & 3) << 2;   // 0,4,8,12

    // W tile load mapping: linear float4
    const int wk = tid >> 4;          // 0..15
    const int wc = (tid & 15) << 2;   // 0..60

    float acc[8][8];
    #pragma unroll
    for (int i = 0; i < 8; ++i)
        #pragma unroll
        for (int j = 0; j < 8; ++j) acc[i][j] = 0.f;

    float4 xreg[4];
    float4 wreg;

    // prefetch k-tile 0
    #pragma unroll
    for (int p = 0; p < 4; ++p) {
        const int r = rowBase + lr + 64 * p;
        xreg[p] = (r < N_NODES) ? *(const float4*)&X[(size_t)r * IN_SIZE + lk]
                                : make_float4(0.f, 0.f, 0.f, 0.f);
    }
    wreg = *(const float4*)&W[(size_t)wk * OUT_SIZE + wc];

    for (int kt = 0; kt < IN_SIZE / 16; ++kt) {
        __syncthreads();
        // stage current k-tile into smem (X transposed)
        #pragma unroll
        for (int p = 0; p < 4; ++p) {
            const int r = lr + 64 * p;
            XsT[lk + 0][r] = xreg[p].x;
            XsT[lk + 1][r] = xreg[p].y;
            XsT[lk + 2][r] = xreg[p].z;
            XsT[lk + 3][r] = xreg[p].w;
        }
        *(float4*)&Ws[wk][wc] = wreg;
        __syncthreads();

        // prefetch next k-tile (overlaps with compute below)
        if (kt < IN_SIZE / 16 - 1) {
            const int kc = (kt + 1) * 16;
            #pragma unroll
            for (int p = 0; p < 4; ++p) {
                const int r = rowBase + lr + 64 * p;
                xreg[p] = (r < N_NODES) ? *(const float4*)&X[(size_t)r * IN_SIZE + kc + lk]
                                        : make_float4(0.f, 0.f, 0.f, 0.f);
            }
            wreg = *(const float4*)&W[(size_t)(kc + wk) * OUT_SIZE + wc];
        }

        #pragma unroll
        for (int k = 0; k < 16; ++k) {
            const float4 xa = *(const float4*)&XsT[k][tr * 8];
            const float4 xb = *(const float4*)&XsT[k][tr * 8 + 4];
            const float4 wa = *(const float4*)&Ws[k][tc * 8];
            const float4 wb = *(const float4*)&Ws[k][tc * 8 + 4];
            const float xv[8] = {xa.x, xa.y, xa.z, xa.w, xb.x, xb.y, xb.z, xb.w};
            const float wv[8] = {wa.x, wa.y, wa.z, wa.w, wb.x, wb.y, wb.z, wb.w};
            #pragma unroll
            for (int i = 0; i < 8; ++i)
                #pragma unroll
                for (int j = 0; j < 8; ++j)
                    acc[i][j] += xv[i] * wv[j];
        }
    }

    // epilogue: add bias, store float4 pairs
    const float4 b0 = *(const float4*)&b[tc * 8];
    const float4 b1 = *(const float4*)&b[tc * 8 + 4];
    #pragma unroll
    for (int i = 0; i < 8; ++i) {
        const int r = rowBase + tr * 8 + i;
        if (r < N_NODES) {
            float4 o0 = make_float4(acc[i][0] + b0.x, acc[i][1] + b0.y,
                                    acc[i][2] + b0.z, acc[i][3] + b0.w);
            float4 o1 = make_float4(acc[i][4] + b1.x, acc[i][5] + b1.y,
                                    acc[i][6] + b1.z, acc[i][7] + b1.w);
            *(float4*)&g_buf0[(size_t)r * OUT_SIZE + tc * 8]     = o0;
            *(float4*)&g_buf0[(size_t)r * OUT_SIZE + tc * 8 + 4] = o1;
        }
    }
}

// ---------------------------------------------------------------------------
// 5) Propagation: one warp per node.
//    new[t] = (deg>0) ? (in[t] + sum_{e in seg(t)} in[src[e]]) / (deg+1) : 0
// ---------------------------------------------------------------------------
__global__ __launch_bounds__(256) void prop_kernel(float* __restrict__ dout, int stage) {
    const int gw   = (blockIdx.x * blockDim.x + threadIdx.x) >> 5;
    const int lane = threadIdx.x & 31;
    if (gw >= N_NODES) return;
    const int t = gw;

    const float2* __restrict__ in2  = (stage == 0) ? (const float2*)g_buf0 : (const float2*)g_buf1;
    float2*       __restrict__ out2 = (stage == 0) ? (float2*)g_buf1       : (float2*)dout;

    const int start = g_rowptr[t];
    const int end   = g_rowptr[t + 1];
    const int deg   = end - start;

    if (deg == 0) {
        out2[t * 32 + lane] = make_float2(0.f, 0.f);
        return;
    }

    float2 acc = make_float2(0.f, 0.f);
    int e = start;
    for (; e + 4 <= end; e += 4) {
        const int s0 = __ldg(&g_src32[e + 0]);
        const int s1 = __ldg(&g_src32[e + 1]);
        const int s2 = __ldg(&g_src32[e + 2]);
        const int s3 = __ldg(&g_src32[e + 3]);
        const float2 v0 = __ldg(&in2[s0 * 32 + lane]);
        const float2 v1 = __ldg(&in2[s1 * 32 + lane]);
        const float2 v2 = __ldg(&in2[s2 * 32 + lane]);
        const float2 v3 = __ldg(&in2[s3 * 32 + lane]);
        acc.x += (v0.x + v1.x) + (v2.x + v3.x);
        acc.y += (v0.y + v1.y) + (v2.y + v3.y);
    }
    for (; e < end; ++e) {
        const int s = __ldg(&g_src32[e]);
        const float2 v = __ldg(&in2[s * 32 + lane]);
        acc.x += v.x; acc.y += v.y;
    }

    const float2 own = __ldg(&in2[t * 32 + lane]);
    const float sc = 1.0f / (float)(deg + 1);
    float2 r = make_float2((acc.x + own.x) * sc, (acc.y + own.y) * sc);
    if (stage == 1) { r.x = fmaxf(r.x, 0.f); r.y = fmaxf(r.y, 0.f); }
    out2[t * 32 + lane] = r;
}

// ---------------------------------------------------------------------------
// Launch. Inputs (metadata order): data, W, b, src_idx, tgt_idx
// ---------------------------------------------------------------------------
extern "C" void kernel_launch(void* const* d_in, const int* in_sizes, int n_in,
                              void* d_out, int out_size) {
    const float* X = (const float*)d_in[0];
    const float* W = (const float*)d_in[1];
    const float* b = (const float*)d_in[2];
    const void*  src = d_in[3];
    const void*  tgt = d_in[4];
    float* out = (float*)d_out;

    detect_kernel<<<1, 32>>>(src);
    convert_kernel<<<(N_EDGES + 255) / 256, 256>>>(src, tgt);
    rowptr_kernel<<<(N_NODES + 1 + 255) / 256, 256>>>();
    gemm_kernel<<<(N_NODES + 255) / 256, 256>>>(X, W, b);
    const int propBlocks = (N_NODES * 32 + 255) / 256;  // 1 warp/node
    prop_kernel<<<propBlocks, 256>>>(out, 0);
    prop_kernel<<<propBlocks, 256>>>(out, 1);
}